// round 15
// baseline (speedup 1.0000x reference)
#include <cuda_runtime.h>
#include <cuda_fp16.h>
#include <cstdint>
#include <math.h>

#define DEV_INLINE __device__ __forceinline__

// Fixed problem dims
#define MAX_B 2048
#define MAX_N 16384
#define MAX_C 2048
#define NTMAX 128

// ---- device-global scratch (referenced only from device code) ----
__device__ __align__(16) __half g_feats[MAX_B * MAX_C];        // 8.4 MB
__device__ __align__(16) __half g_fs[(size_t)MAX_N * MAX_C];   // 67 MB
__device__ __align__(16) float g_pos_part[(size_t)MAX_B * NTMAX];
__device__ __align__(16) float g_neg_part[(size_t)MAX_B * NTMAX];
__device__ __align__(16) float g_loss[MAX_B];

// ---------------- helpers ----------------
DEV_INLINE uint32_t smem_u32(const void* p) {
    uint32_t a;
    asm("{ .reg .u64 t; cvta.to.shared.u64 t, %1; cvt.u32.u64 %0, t; }"
        : "=r"(a) : "l"(p));
    return a;
}

DEV_INLINE uint32_t swz(uint32_t off) {            // SW128-style xor swizzle
    return off ^ ((off >> 3) & 0x70);
}

DEV_INLINE void cp16(uint32_t s, const void* g) {
    asm volatile("cp.async.cg.shared.global [%0], [%1], 16;\n"
                 :: "r"(s), "l"(g));
}
#define CP_COMMIT() asm volatile("cp.async.commit_group;\n" ::: "memory")
#define CP_WAIT2()  asm volatile("cp.async.wait_group 2;\n" ::: "memory")

#define LDSM4(R, addr)                                                        \
    asm volatile("ldmatrix.sync.aligned.m8n8.x4.shared.b16 {%0,%1,%2,%3},[%4];" \
                 : "=r"((R)[0]), "=r"((R)[1]), "=r"((R)[2]), "=r"((R)[3])     \
                 : "r"(addr))

#define MMAF16(d, a, b0, b1)                                                  \
    asm volatile(                                                             \
        "mma.sync.aligned.m16n8k16.row.col.f16.f16.f16.f16 "                  \
        "{%0,%1},{%2,%3,%4,%5},{%6,%7},{%0,%1};"                              \
        : "+r"((d)[0]), "+r"((d)[1])                                          \
        : "r"((a)[0]), "r"((a)[1]), "r"((a)[2]), "r"((a)[3]),                 \
          "r"(b0), "r"(b1))

// ---------------- kernels ----------------

// fp32 -> fp16 conversion into device-global scratch
__global__ void k_cvt(const float* __restrict__ src, long n4, int which) {
    __half* dst = which ? g_fs : g_feats;
    long i = (long)blockIdx.x * blockDim.x + threadIdx.x;
    long stride = (long)gridDim.x * blockDim.x;
    const float4* s4 = (const float4*)src;
    __half2* d2 = (__half2*)dst;
    for (long j = i; j < n4; j += stride) {
        float4 v = s4[j];
        d2[2 * j]     = __floats2half2_rn(v.x, v.y);
        d2[2 * j + 1] = __floats2half2_rn(v.z, v.w);
    }
}

// GEMM tile config: BN=128, 8 warps of 64x32, 3 stages, 2 CTAs/SM
#define BM 128
#define BN 128
#define BK 64
#define STAGES 3
#define A_BYTES (BM * BK * 2)               // 16384
#define B_BYTES (BN * BK * 2)               // 16384
#define STAGE_BYTES (A_BYTES + B_BYTES)     // 32768
#define SM_SLAB (STAGES * STAGE_BYTES)      // 98304 : labels [128]
#define SM_REDP (SM_SLAB + 512)             // [4][128] floats
#define SM_REDN (SM_REDP + 2048)
#define SMEM_SZ (SM_REDN + 2048)            // 102912 -> 2 CTAs/SM

DEV_INLINE void load_stage(uint32_t sb, int stage, int kc,
                           const __half* pa, const __half* pb,
                           int tid, int C) {
    uint32_t sA = sb + stage * STAGE_BYTES;
    uint32_t sB = sA + A_BYTES;
    const __half* a0 = pa + (size_t)kc * BK;
    const __half* b0 = pb + (size_t)kc * BK;
#pragma unroll
    for (int j = 0; j < 4; j++) {                   // A: 1024 16B-chunks / 256 thr
        int id = tid + j * 256;
        int r = id >> 3, c = id & 7;
        uint32_t off = swz((uint32_t)(r * 128 + c * 16));
        cp16(sA + off, a0 + (size_t)r * C + c * 8);
    }
#pragma unroll
    for (int j = 0; j < 4; j++) {                   // B: 1024 16B-chunks / 256 thr
        int id = tid + j * 256;
        int r = id >> 3, c = id & 7;
        uint32_t off = swz((uint32_t)(r * 128 + c * 16));
        cp16(sB + off, b0 + (size_t)r * C + c * 8);
    }
}

// GEMM + fused exp/mask/min/sum epilogue.
// grid = (B/128, N/128); blockIdx.x fastest -> B col-tile reused in L2.
__global__ __launch_bounds__(256, 2)
void k_gemm(const int* __restrict__ labels, const int* __restrict__ labels_s,
            int Bq, int N, int C) {
    extern __shared__ unsigned char smem[];
    uint32_t sb = smem_u32(smem);
    int tid = threadIdx.x;
    int lane = tid & 31, wid = tid >> 5;
    int warp_m = wid >> 2, warp_n = wid & 3;       // 2 x 4 warps of 64x32
    int row0 = blockIdx.x * BM;
    int col0 = blockIdx.y * BN;

    int* slab = (int*)(smem + SM_SLAB);
    if (tid < 128) slab[tid] = labels_s[col0 + tid];

    const __half* pa = g_feats + (size_t)row0 * C;
    const __half* pb = g_fs + (size_t)col0 * C;

    uint32_t acc[4][4][2];                          // f16x2 accumulators
#pragma unroll
    for (int i = 0; i < 4; i++)
#pragma unroll
        for (int j = 0; j < 4; j++) { acc[i][j][0] = 0u; acc[i][j][1] = 0u; }

    int KC = C / BK;                                // 32
    load_stage(sb, 0, 0, pa, pb, tid, C); CP_COMMIT();
    load_stage(sb, 1, 1, pa, pb, tid, C); CP_COMMIT();

    int lrow = lane & 15;
    int lcolb = (lane >> 4) << 4;                   // byte col offset 0/16
    uint32_t kxor = (uint32_t)((lrow & 7) << 4);    // swizzle xor (row&7 == lrow&7)
    uint32_t arow[4], brow[2];
#pragma unroll
    for (int mi = 0; mi < 4; mi++)
        arow[mi] = (uint32_t)((warp_m * 64 + mi * 16 + lrow) * 128);
#pragma unroll
    for (int g = 0; g < 2; g++)
        brow[g] = (uint32_t)((warp_n * 32 + g * 16 + lrow) * 128);

    uint32_t a[2][4][4], b[2][2][4];                // double-buffered fragments

    for (int kc = 0; kc < KC; kc++) {
        __syncthreads();                            // stage (kc+2)%3 free to overwrite
        if (kc + 2 < KC) load_stage(sb, (kc + 2) % STAGES, kc + 2, pa, pb, tid, C);
        CP_COMMIT();
        CP_WAIT2();                                 // stage kc data arrived (this thread)
        __syncthreads();                            // ... and all threads'

        uint32_t stA = sb + (kc % STAGES) * STAGE_BYTES;
        uint32_t stB = stA + A_BYTES;

        {   // prime ks=0 into buffer 0
            uint32_t kb = lcolb ^ kxor;
#pragma unroll
            for (int mi = 0; mi < 4; mi++) LDSM4(a[0][mi], stA + arow[mi] + kb);
#pragma unroll
            for (int g = 0; g < 2; g++)    LDSM4(b[0][g], stB + brow[g] + kb);
        }
#pragma unroll
        for (int ks = 0; ks < 4; ks++) {
            int cur = ks & 1, nxt = cur ^ 1;
            if (ks < 3) {                           // prefetch ks+1 fragments
                uint32_t kb = ((uint32_t)((ks + 1) * 32) + lcolb) ^ kxor;
#pragma unroll
                for (int mi = 0; mi < 4; mi++) LDSM4(a[nxt][mi], stA + arow[mi] + kb);
#pragma unroll
                for (int g = 0; g < 2; g++)    LDSM4(b[nxt][g], stB + brow[g] + kb);
            }
#pragma unroll
            for (int mi = 0; mi < 4; mi++) {
#pragma unroll
                for (int nj = 0; nj < 4; nj++) {
                    int g = nj >> 1;
                    if (nj & 1) { MMAF16(acc[mi][nj], a[cur][mi], b[cur][g][1], b[cur][g][3]); }
                    else        { MMAF16(acc[mi][nj], a[cur][mi], b[cur][g][0], b[cur][g][2]); }
                }
            }
        }
    }

    // ---- fused epilogue ----
    // f16-acc layout: reg0 = {row r, cols c0,c0+1}, reg1 = {row r+8, cols c0,c0+1}
    int rbase = warp_m * 64 + (lane >> 2);
    int labr[8];
#pragma unroll
    for (int mi = 0; mi < 4; mi++) {
        labr[mi * 2]     = labels[row0 + rbase + mi * 16];
        labr[mi * 2 + 1] = labels[row0 + rbase + mi * 16 + 8];
    }
    int labc[8];
#pragma unroll
    for (int nj = 0; nj < 4; nj++) {
        int c0 = warp_n * 32 + nj * 8 + 2 * (lane & 3);
        labc[nj * 2]     = slab[c0];
        labc[nj * 2 + 1] = slab[c0 + 1];
    }
    float pm[8], ns[8];
#pragma unroll
    for (int i = 0; i < 8; i++) { pm[i] = INFINITY; ns[i] = 0.0f; }

#pragma unroll
    for (int mi = 0; mi < 4; mi++) {
#pragma unroll
        for (int nj = 0; nj < 4; nj++) {
            __half2 h01 = *reinterpret_cast<__half2*>(&acc[mi][nj][0]);
            __half2 h23 = *reinterpret_cast<__half2*>(&acc[mi][nj][1]);
            float2 v01 = __half22float2(h01);
            float2 v23 = __half22float2(h23);
            float e0 = __expf(v01.x * 20.0f);
            float e1 = __expf(v01.y * 20.0f);
            float e2 = __expf(v23.x * 20.0f);
            float e3 = __expf(v23.y * 20.0f);
            int l0 = labc[nj * 2], l1 = labc[nj * 2 + 1];
            int r0 = labr[mi * 2], r1 = labr[mi * 2 + 1];
            if (l0 == r0) pm[mi * 2] = fminf(pm[mi * 2], e0); else ns[mi * 2] += e0;
            if (l1 == r0) pm[mi * 2] = fminf(pm[mi * 2], e1); else ns[mi * 2] += e1;
            if (l0 == r1) pm[mi * 2 + 1] = fminf(pm[mi * 2 + 1], e2); else ns[mi * 2 + 1] += e2;
            if (l1 == r1) pm[mi * 2 + 1] = fminf(pm[mi * 2 + 1], e3); else ns[mi * 2 + 1] += e3;
        }
    }
#pragma unroll
    for (int i = 0; i < 8; i++) {
        pm[i] = fminf(pm[i], __shfl_xor_sync(0xFFFFFFFFu, pm[i], 1));
        pm[i] = fminf(pm[i], __shfl_xor_sync(0xFFFFFFFFu, pm[i], 2));
        ns[i] += __shfl_xor_sync(0xFFFFFFFFu, ns[i], 1);
        ns[i] += __shfl_xor_sync(0xFFFFFFFFu, ns[i], 2);
    }

    float* red_p = (float*)(smem + SM_REDP);   // [4][128]
    float* red_n = (float*)(smem + SM_REDN);
    if ((lane & 3) == 0) {
#pragma unroll
        for (int mi = 0; mi < 4; mi++) {
            int r = warp_m * 64 + mi * 16 + (lane >> 2);
            red_p[warp_n * 128 + r] = pm[mi * 2];
            red_n[warp_n * 128 + r] = ns[mi * 2];
            red_p[warp_n * 128 + r + 8] = pm[mi * 2 + 1];
            red_n[warp_n * 128 + r + 8] = ns[mi * 2 + 1];
        }
    }
    __syncthreads();
    if (tid < 128) {
        float p = INFINITY, n = 0.0f;
#pragma unroll
        for (int w = 0; w < 4; w++) {
            p = fminf(p, red_p[w * 128 + tid]);
            n += red_n[w * 128 + tid];
        }
        int nt = N / BN;
        g_pos_part[(size_t)(row0 + tid) * nt + blockIdx.y] = p;
        g_neg_part[(size_t)(row0 + tid) * nt + blockIdx.y] = n;
    }
}

// per-row reduce of col-tile partials -> loss[row]  (deterministic tree)
__global__ void k_row(int nt) {
    int row = blockIdx.x, t = threadIdx.x;
    __shared__ float spm[128], sns[128];
    float pmv = INFINITY, nsv = 0.0f;
    if (t < nt) {
        pmv = g_pos_part[(size_t)row * nt + t];
        nsv = g_neg_part[(size_t)row * nt + t];
    }
    spm[t] = pmv; sns[t] = nsv;
    __syncthreads();
    for (int st = 64; st > 0; st >>= 1) {
        if (t < st) {
            spm[t] = fminf(spm[t], spm[t + st]);
            sns[t] += sns[t + st];
        }
        __syncthreads();
    }
    if (t == 0) {
        float p = spm[0], n = sns[0];
        g_loss[row] = -logf(p / (p + n + 1e-6f) + 1e-6f);
    }
}

// mean over rows -> scalar output
__global__ void k_mean(float* __restrict__ out, int Bq) {
    __shared__ float s[1024];
    float accv = 0.0f;
    for (int i = threadIdx.x; i < Bq; i += 1024) accv += g_loss[i];
    s[threadIdx.x] = accv;
    __syncthreads();
    for (int st = 512; st > 0; st >>= 1) {
        if (threadIdx.x < st) s[threadIdx.x] += s[threadIdx.x + st];
        __syncthreads();
    }
    if (threadIdx.x == 0) out[0] = s[0] / (float)Bq;
}

extern "C" void kernel_launch(void* const* d_in, const int* in_sizes, int n_in,
                              void* d_out, int out_size) {
    const float* feats    = (const float*)d_in[0];
    const float* feats_s  = (const float*)d_in[1];
    const int*   labels   = (const int*)d_in[2];
    const int*   labels_s = (const int*)d_in[3];

    int Bq = in_sizes[2];            // 2048
    int N  = in_sizes[3];            // 16384
    int C  = in_sizes[0] / Bq;       // 2048

    long nA4 = ((long)Bq * C) / 4;
    long nB4 = ((long)N * C) / 4;
    k_cvt<<<2048, 256>>>(feats,   nA4, 0);
    k_cvt<<<4096, 256>>>(feats_s, nB4, 1);

    cudaFuncSetAttribute(k_gemm, cudaFuncAttributeMaxDynamicSharedMemorySize, SMEM_SZ);
    dim3 grid(Bq / BM, N / BN);
    k_gemm<<<grid, 256, SMEM_SZ>>>(labels, labels_s, Bq, N, C);

    k_row<<<Bq, 128>>>(N / BN);
    k_mean<<<1, 1024>>>((float*)d_out, Bq);
}

// round 17
// speedup vs baseline: 1.5198x; 1.5198x over previous
#include <cuda_runtime.h>
#include <cuda_fp16.h>
#include <cstdint>
#include <math.h>

#define DEV_INLINE __device__ __forceinline__

// Fixed problem dims
#define MAX_B 2048
#define MAX_N 16384
#define MAX_C 2048
#define NTMAX 128

// ---- device-global scratch (referenced only from device code) ----
__device__ __align__(16) __half g_feats[MAX_B * MAX_C];        // 8.4 MB
__device__ __align__(16) __half g_fs[(size_t)MAX_N * MAX_C];   // 67 MB
__device__ __align__(16) float g_pos_part[(size_t)MAX_B * NTMAX];
__device__ __align__(16) float g_neg_part[(size_t)MAX_B * NTMAX];
__device__ __align__(16) float g_loss[MAX_B];

// ---------------- helpers ----------------
DEV_INLINE uint32_t smem_u32(const void* p) {
    uint32_t a;
    asm("{ .reg .u64 t; cvta.to.shared.u64 t, %1; cvt.u32.u64 %0, t; }"
        : "=r"(a) : "l"(p));
    return a;
}

DEV_INLINE uint32_t swz(uint32_t off) {            // SW128-style xor swizzle
    return off ^ ((off >> 3) & 0x70);
}

DEV_INLINE void cp16(uint32_t s, const void* g) {
    asm volatile("cp.async.cg.shared.global [%0], [%1], 16;\n"
                 :: "r"(s), "l"(g));
}
#define CP_COMMIT() asm volatile("cp.async.commit_group;\n" ::: "memory")
#define CP_WAIT1()  asm volatile("cp.async.wait_group 1;\n" ::: "memory")

#define LDSM4(R, addr)                                                        \
    asm volatile("ldmatrix.sync.aligned.m8n8.x4.shared.b16 {%0,%1,%2,%3},[%4];" \
                 : "=r"((R)[0]), "=r"((R)[1]), "=r"((R)[2]), "=r"((R)[3])     \
                 : "r"(addr))

#define MMAF16(d, a, b0, b1)                                                  \
    asm volatile(                                                             \
        "mma.sync.aligned.m16n8k16.row.col.f16.f16.f16.f16 "                  \
        "{%0,%1},{%2,%3,%4,%5},{%6,%7},{%0,%1};"                              \
        : "+r"((d)[0]), "+r"((d)[1])                                          \
        : "r"((a)[0]), "r"((a)[1]), "r"((a)[2]), "r"((a)[3]),                 \
          "r"(b0), "r"(b1))

// ---------------- kernels ----------------

// fp32 -> fp16 conversion into device-global scratch
__global__ void k_cvt(const float* __restrict__ src, long n4, int which) {
    __half* dst = which ? g_fs : g_feats;
    long i = (long)blockIdx.x * blockDim.x + threadIdx.x;
    long stride = (long)gridDim.x * blockDim.x;
    const float4* s4 = (const float4*)src;
    __half2* d2 = (__half2*)dst;
    for (long j = i; j < n4; j += stride) {
        float4 v = s4[j];
        d2[2 * j]     = __floats2half2_rn(v.x, v.y);
        d2[2 * j + 1] = __floats2half2_rn(v.z, v.w);
    }
}

// GEMM tile config: 8 warps of 64x64, BK=128, 2 stages, two-barrier sync
#define BM 128
#define BN 256
#define BK 128
#define KS_PER_KC (BK / 16)                 // 8
#define A_BYTES (BM * BK * 2)               // 32768
#define B_BYTES (BN * BK * 2)               // 65536
#define STAGE_BYTES (A_BYTES + B_BYTES)     // 98304
#define STAGES 2
#define SM_SLAB (STAGES * STAGE_BYTES)      // 196608 : labels [256]
#define SM_REDP (SM_SLAB + 1024)            // [4][128] floats
#define SM_REDN (SM_REDP + 2048)
#define SMEM_SZ (SM_REDN + 2048)            // 201728

// Tile stored as TWO K-panels of 64 halves each; panel p holds K
// [p*64, p*64+64) in the proven 128-byte-row swizzled layout.
#define A_PANEL (BM * 64 * 2)               // 16384
#define B_PANEL (BN * 64 * 2)               // 32768

DEV_INLINE void load_stage(uint32_t sb, int stage, int kc,
                           const __half* pa, const __half* pb,
                           int tid, int C) {
    uint32_t sA = sb + stage * STAGE_BYTES;
    uint32_t sB = sA + A_BYTES;
    const __half* a0 = pa + (size_t)kc * BK;
    const __half* b0 = pb + (size_t)kc * BK;
#pragma unroll
    for (int p = 0; p < 2; p++) {                   // two 64-half K panels
#pragma unroll
        for (int j = 0; j < 4; j++) {               // A: 1024 chunks/panel
            int id = tid + j * 256;
            int r = id >> 3, c = id & 7;
            uint32_t off = swz((uint32_t)(r * 128 + c * 16));
            cp16(sA + p * A_PANEL + off, a0 + (size_t)r * C + p * 64 + c * 8);
        }
#pragma unroll
        for (int j = 0; j < 8; j++) {               // B: 2048 chunks/panel
            int id = tid + j * 256;
            int r = id >> 3, c = id & 7;
            uint32_t off = swz((uint32_t)(r * 128 + c * 16));
            cp16(sB + p * B_PANEL + off, b0 + (size_t)r * C + p * 64 + c * 8);
        }
    }
}

// GEMM + fused exp/mask/min/sum epilogue.
// grid = (B/128, N/256); blockIdx.x fastest -> B col-tile reused in L2.
__global__ __launch_bounds__(256, 1)
void k_gemm(const int* __restrict__ labels, const int* __restrict__ labels_s,
            int Bq, int N, int C) {
    extern __shared__ unsigned char smem[];
    uint32_t sb = smem_u32(smem);
    int tid = threadIdx.x;
    int lane = tid & 31, wid = tid >> 5;
    int warp_m = wid >> 2, warp_n = wid & 3;       // 2 x 4 warps of 64x64
    int row0 = blockIdx.x * BM;
    int col0 = blockIdx.y * BN;

    int* slab = (int*)(smem + SM_SLAB);
    slab[tid] = labels_s[col0 + tid];              // 256 labels, 256 threads

    const __half* pa = g_feats + (size_t)row0 * C;
    const __half* pb = g_fs + (size_t)col0 * C;

    uint32_t acc[4][8][2];                          // f16x2 accumulators
#pragma unroll
    for (int i = 0; i < 4; i++)
#pragma unroll
        for (int j = 0; j < 8; j++) { acc[i][j][0] = 0u; acc[i][j][1] = 0u; }

    int KC = C / BK;                                // 16
    load_stage(sb, 0, 0, pa, pb, tid, C); CP_COMMIT();

    int lrow = lane & 15;
    int lcolb = (lane >> 4) << 4;                   // byte col offset 0/16
    uint32_t kxor = (uint32_t)((lrow & 7) << 4);    // swizzle xor (row&7 == lrow&7)
    uint32_t arow[4], brow[4];
#pragma unroll
    for (int mi = 0; mi < 4; mi++)
        arow[mi] = (uint32_t)((warp_m * 64 + mi * 16 + lrow) * 128);
#pragma unroll
    for (int g = 0; g < 4; g++)
        brow[g] = (uint32_t)((warp_n * 64 + g * 16 + lrow) * 128);

    uint32_t a[2][4][4], b[2][4][4];                // double-buffered fragments

    for (int kc = 0; kc < KC; kc++) {
        // Two-barrier scheme (proven R12 ordering), 16 iterations total:
        // sync1: all readers of slot (kc+1)&1 (iteration kc-1) are done.
        __syncthreads();
        if (kc + 1 < KC) load_stage(sb, (kc + 1) & 1, kc + 1, pa, pb, tid, C);
        CP_COMMIT();                                // unconditional (may be empty)
        CP_WAIT1();                                 // my groups: stage kc done
        __syncthreads();                            // everyone's stage kc done

        uint32_t stA = sb + (kc & 1) * STAGE_BYTES;
        uint32_t stB = stA + A_BYTES;

        {   // prime ks=0 (panel 0) into buffer 0
            uint32_t kb = lcolb ^ kxor;
#pragma unroll
            for (int mi = 0; mi < 4; mi++) LDSM4(a[0][mi], stA + arow[mi] + kb);
#pragma unroll
            for (int g = 0; g < 4; g++)    LDSM4(b[0][g], stB + brow[g] + kb);
        }
#pragma unroll
        for (int ks = 0; ks < KS_PER_KC; ks++) {
            int cur = ks & 1, nxt = cur ^ 1;
            if (ks < KS_PER_KC - 1) {               // prefetch ks+1 fragments
                int ksn = ks + 1;
                uint32_t pA = (uint32_t)((ksn >> 2) * A_PANEL);
                uint32_t pB = (uint32_t)((ksn >> 2) * B_PANEL);
                uint32_t kb = ((uint32_t)((ksn & 3) * 32) + lcolb) ^ kxor;
#pragma unroll
                for (int mi = 0; mi < 4; mi++)
                    LDSM4(a[nxt][mi], stA + pA + arow[mi] + kb);
#pragma unroll
                for (int g = 0; g < 4; g++)
                    LDSM4(b[nxt][g], stB + pB + brow[g] + kb);
            }
#pragma unroll
            for (int mi = 0; mi < 4; mi++) {
#pragma unroll
                for (int nj = 0; nj < 8; nj++) {
                    int g = nj >> 1;
                    if (nj & 1) { MMAF16(acc[mi][nj], a[cur][mi], b[cur][g][1], b[cur][g][3]); }
                    else        { MMAF16(acc[mi][nj], a[cur][mi], b[cur][g][0], b[cur][g][2]); }
                }
            }
        }
    }

    // ---- fused epilogue ----
    // f16-acc layout: reg0 = {row r, cols c0,c0+1}, reg1 = {row r+8, cols c0,c0+1}
    int rbase = warp_m * 64 + (lane >> 2);
    int labr[8];
#pragma unroll
    for (int mi = 0; mi < 4; mi++) {
        labr[mi * 2]     = labels[row0 + rbase + mi * 16];
        labr[mi * 2 + 1] = labels[row0 + rbase + mi * 16 + 8];
    }
    int labc[16];
#pragma unroll
    for (int nj = 0; nj < 8; nj++) {
        int c0 = warp_n * 64 + nj * 8 + 2 * (lane & 3);
        labc[nj * 2]     = slab[c0];
        labc[nj * 2 + 1] = slab[c0 + 1];
    }
    float pm[8], ns[8];
#pragma unroll
    for (int i = 0; i < 8; i++) { pm[i] = INFINITY; ns[i] = 0.0f; }

#pragma unroll
    for (int mi = 0; mi < 4; mi++) {
#pragma unroll
        for (int nj = 0; nj < 8; nj++) {
            __half2 h01 = *reinterpret_cast<__half2*>(&acc[mi][nj][0]);
            __half2 h23 = *reinterpret_cast<__half2*>(&acc[mi][nj][1]);
            float2 v01 = __half22float2(h01);
            float2 v23 = __half22float2(h23);
            float e0 = __expf(v01.x * 20.0f);
            float e1 = __expf(v01.y * 20.0f);
            float e2 = __expf(v23.x * 20.0f);
            float e3 = __expf(v23.y * 20.0f);
            int l0 = labc[nj * 2], l1 = labc[nj * 2 + 1];
            int r0 = labr[mi * 2], r1 = labr[mi * 2 + 1];
            if (l0 == r0) pm[mi * 2] = fminf(pm[mi * 2], e0); else ns[mi * 2] += e0;
            if (l1 == r0) pm[mi * 2] = fminf(pm[mi * 2], e1); else ns[mi * 2] += e1;
            if (l0 == r1) pm[mi * 2 + 1] = fminf(pm[mi * 2 + 1], e2); else ns[mi * 2 + 1] += e2;
            if (l1 == r1) pm[mi * 2 + 1] = fminf(pm[mi * 2 + 1], e3); else ns[mi * 2 + 1] += e3;
        }
    }
#pragma unroll
    for (int i = 0; i < 8; i++) {
        pm[i] = fminf(pm[i], __shfl_xor_sync(0xFFFFFFFFu, pm[i], 1));
        pm[i] = fminf(pm[i], __shfl_xor_sync(0xFFFFFFFFu, pm[i], 2));
        ns[i] += __shfl_xor_sync(0xFFFFFFFFu, ns[i], 1);
        ns[i] += __shfl_xor_sync(0xFFFFFFFFu, ns[i], 2);
    }

    float* red_p = (float*)(smem + SM_REDP);   // [4][128]
    float* red_n = (float*)(smem + SM_REDN);
    if ((lane & 3) == 0) {
#pragma unroll
        for (int mi = 0; mi < 4; mi++) {
            int r = warp_m * 64 + mi * 16 + (lane >> 2);
            red_p[warp_n * 128 + r] = pm[mi * 2];
            red_n[warp_n * 128 + r] = ns[mi * 2];
            red_p[warp_n * 128 + r + 8] = pm[mi * 2 + 1];
            red_n[warp_n * 128 + r + 8] = ns[mi * 2 + 1];
        }
    }
    __syncthreads();
    if (tid < 128) {
        float p = INFINITY, n = 0.0f;
#pragma unroll
        for (int w = 0; w < 4; w++) {
            p = fminf(p, red_p[w * 128 + tid]);
            n += red_n[w * 128 + tid];
        }
        int nt = N / BN;
        g_pos_part[(size_t)(row0 + tid) * nt + blockIdx.y] = p;
        g_neg_part[(size_t)(row0 + tid) * nt + blockIdx.y] = n;
    }
}

// per-row reduce of col-tile partials -> loss[row]  (deterministic tree)
__global__ void k_row(int nt) {
    int row = blockIdx.x, t = threadIdx.x;
    __shared__ float spm[128], sns[128];
    float pmv = INFINITY, nsv = 0.0f;
    if (t < nt) {
        pmv = g_pos_part[(size_t)row * nt + t];
        nsv = g_neg_part[(size_t)row * nt + t];
    }
    spm[t] = pmv; sns[t] = nsv;
    __syncthreads();
    for (int st = 64; st > 0; st >>= 1) {
        if (t < st) {
            spm[t] = fminf(spm[t], spm[t + st]);
            sns[t] += sns[t + st];
        }
        __syncthreads();
    }
    if (t == 0) {
        float p = spm[0], n = sns[0];
        g_loss[row] = -logf(p / (p + n + 1e-6f) + 1e-6f);
    }
}

// mean over rows -> scalar output
__global__ void k_mean(float* __restrict__ out, int Bq) {
    __shared__ float s[1024];
    float accv = 0.0f;
    for (int i = threadIdx.x; i < Bq; i += 1024) accv += g_loss[i];
    s[threadIdx.x] = accv;
    __syncthreads();
    for (int st = 512; st > 0; st >>= 1) {
        if (threadIdx.x < st) s[threadIdx.x] += s[threadIdx.x + st];
        __syncthreads();
    }
    if (threadIdx.x == 0) out[0] = s[0] / (float)Bq;
}

extern "C" void kernel_launch(void* const* d_in, const int* in_sizes, int n_in,
                              void* d_out, int out_size) {
    const float* feats    = (const float*)d_in[0];
    const float* feats_s  = (const float*)d_in[1];
    const int*   labels   = (const int*)d_in[2];
    const int*   labels_s = (const int*)d_in[3];

    int Bq = in_sizes[2];            // 2048
    int N  = in_sizes[3];            // 16384
    int C  = in_sizes[0] / Bq;       // 2048

    long nA4 = ((long)Bq * C) / 4;
    long nB4 = ((long)N * C) / 4;
    k_cvt<<<2048, 256>>>(feats,   nA4, 0);
    k_cvt<<<4096, 256>>>(feats_s, nB4, 1);

    cudaFuncSetAttribute(k_gemm, cudaFuncAttributeMaxDynamicSharedMemorySize, SMEM_SZ);
    dim3 grid(Bq / BM, N / BN);
    k_gemm<<<grid, 256, SMEM_SZ>>>(labels, labels_s, Bq, N, C);

    k_row<<<Bq, 128>>>(N / BN);
    k_mean<<<1, 1024>>>((float*)d_out, Bq);
}